// round 12
// baseline (speedup 1.0000x reference)
#include <cuda_runtime.h>
#include <cuda_fp16.h>
#include <cstdint>

#define N_MAX 8192
#define D_MAX 256
#define BM 128                    // CTA rows (i)
#define BN 256                    // CTA cols (j)
#define BK 64                     // f16 K per stage
#define NBUF 2
#define NTHREADS 256
#define MARGIN 0.5f

__device__ __half g_xh[N_MAX * D_MAX];
__device__ float g_sq[N_MAX];
__device__ int   g_is64;

// dynamic smem layout (bytes)
#define TILE_A_BYTES (BM * BK * 2)                  // 16384
#define TILE_B_BYTES (BN * BK * 2)                  // 32768
#define STAGE_BYTES  (TILE_A_BYTES + TILE_B_BYTES)  // 49152
#define SM_SQI   (NBUF * STAGE_BYTES)               // 98304
#define SM_SQJ   (SM_SQI + BM * 4)
#define SM_TI    (SM_SQJ + BN * 4)
#define SM_TJ    (SM_TI + BM * 4)
#define SM_RED   (SM_TJ + BN * 4)
#define SM_TOTAL (SM_RED + NTHREADS * 4)            // ~101.5 KB -> 2 CTAs/SM

__device__ __forceinline__ uint32_t smem_u32(const void* p) {
    uint32_t a;
    asm("{ .reg .u64 t; cvta.to.shared.u64 t, %1; cvt.u32.u64 %0, t; }" : "=r"(a) : "l"(p));
    return a;
}

// ---------------------------------------------------------------------------
// fused prelim: zero out + int64 detect + exact fp32 norms + f16 copy
// ---------------------------------------------------------------------------
__global__ void cvtsq_kernel(const float* __restrict__ x,
                             const unsigned int* __restrict__ t, int n,
                             float* __restrict__ out) {
    if (blockIdx.x == 0 && threadIdx.x < 32) {
        int lane = threadIdx.x;
        unsigned bad = t[2 * lane + 1] | t[2 * (lane + 32) + 1];
        unsigned ball = __ballot_sync(0xffffffffu, bad != 0u);
        if (lane == 0) { g_is64 = (ball == 0u); out[0] = 0.0f; }
    }

    int row  = blockIdx.x * (blockDim.x >> 5) + (threadIdx.x >> 5);
    int lane = threadIdx.x & 31;
    if (row >= n) return;
    const float* p = x + (size_t)row * D_MAX;

    float4 v0 = *(const float4*)(p + lane * 4);
    float4 v1 = *(const float4*)(p + 128 + lane * 4);

    float s = v0.x * v0.x + v0.y * v0.y + v0.z * v0.z + v0.w * v0.w
            + v1.x * v1.x + v1.y * v1.y + v1.z * v1.z + v1.w * v1.w;
    #pragma unroll
    for (int o = 16; o > 0; o >>= 1) s += __shfl_xor_sync(0xffffffffu, s, o);
    if (lane == 0) g_sq[row] = s;

    __half* dst = g_xh + (size_t)row * D_MAX;
    *(__half2*)(dst + lane * 4)           = __floats2half2_rn(v0.x, v0.y);
    *(__half2*)(dst + lane * 4 + 2)       = __floats2half2_rn(v0.z, v0.w);
    *(__half2*)(dst + 128 + lane * 4)     = __floats2half2_rn(v1.x, v1.y);
    *(__half2*)(dst + 128 + lane * 4 + 2) = __floats2half2_rn(v1.z, v1.w);
}

// ---------------------------------------------------------------------------
// f16 mma.sync (f16 accum) fused gram + loss. CTA 128x256, 8 warps (2m x 4n),
// warp tile 64x64 (0.061 B/MAC smem traffic). 2-deep cp.async buffering,
// 2 CTAs/SM. smem rows: 128B stride; chunk c of row r at r*128+((c^(r&7))<<4).
// Coverage: CTA(bj 256-cols, bi 128-rows), bi in [0, 2bj+2); mask on straddle.
// ---------------------------------------------------------------------------
__global__ __launch_bounds__(NTHREADS, 2)
void loss_kernel(const void* __restrict__ tgt_raw, float* __restrict__ out,
                 float scale) {
    // decode t -> (bj, bi): start(bj) = bj*(bj+1), count = 2bj+2
    const int t = blockIdx.x;
    int bj = (int)((sqrtf(4.0f * (float)t + 1.0f) - 1.0f) * 0.5f);
    while ((bj + 1) * (bj + 2) <= t) bj++;
    while (bj * (bj + 1) > t) bj--;
    const int bi = t - bj * (bj + 1);

    extern __shared__ char smem[];
    float* s_sqi = (float*)(smem + SM_SQI);
    float* s_sqj = (float*)(smem + SM_SQJ);
    int*   s_ti  = (int*)(smem + SM_TI);
    int*   s_tj  = (int*)(smem + SM_TJ);
    float* s_red = (float*)(smem + SM_RED);

    const int tid  = threadIdx.x;
    const int wid  = tid >> 5;
    const int lane = tid & 31;
    const int iBase = bi * BM;
    const int jBase = bj * BN;

    const uint32_t smem_tiles = smem_u32(smem);
    const __half* xa = g_xh + (size_t)iBase * D_MAX;
    const __half* xb = g_xh + (size_t)jBase * D_MAX;

    // A: 1024 16B-chunks (4/thread), B: 2048 (8/thread); row=idx>>3, c=idx&7
    auto load_stage = [&](int kb, int buf) {
        const int k0 = kb * BK;
        const uint32_t sA = smem_tiles + buf * STAGE_BYTES;
        const uint32_t sB = sA + TILE_A_BYTES;
        #pragma unroll
        for (int u = 0; u < 4; u++) {
            int idx = tid * 4 + u;
            int row = idx >> 3;
            int c   = idx & 7;
            uint32_t sw = row * 128 + (((c ^ (row & 7)) & 7) << 4);
            asm volatile("cp.async.cg.shared.global [%0], [%1], 16;"
                         :: "r"(sA + sw), "l"((const void*)(xa + row * D_MAX + k0 + c * 8)) : "memory");
        }
        #pragma unroll
        for (int u = 0; u < 8; u++) {
            int idx = tid * 8 + u;
            int row = idx >> 3;
            int c   = idx & 7;
            uint32_t sw = row * 128 + (((c ^ (row & 7)) & 7) << 4);
            asm volatile("cp.async.cg.shared.global [%0], [%1], 16;"
                         :: "r"(sB + sw), "l"((const void*)(xb + row * D_MAX + k0 + c * 8)) : "memory");
        }
        asm volatile("cp.async.commit_group;" ::: "memory");
    };

    load_stage(0, 0);
    load_stage(1, 1);

    {
        const long long* t64p = (const long long*)tgt_raw;
        const int*       t32p = (const int*)tgt_raw;
        const bool is64 = (g_is64 != 0);
        if (tid < BM) {
            s_sqi[tid] = g_sq[iBase + tid];
            s_ti[tid]  = is64 ? (int)t64p[iBase + tid] : t32p[iBase + tid];
        } else {
            int tt = tid - BM;   // 0..127 -> handles cols tt and tt+128
            s_sqj[tt] = g_sq[jBase + tt];
            s_tj[tt]  = is64 ? (int)t64p[jBase + tt] : t32p[jBase + tt];
            s_sqj[tt + 128] = g_sq[jBase + tt + 128];
            s_tj[tt + 128]  = is64 ? (int)t64p[jBase + tt + 128] : t32p[jBase + tt + 128];
        }
    }

    // warp grid 2m x 4n; warp tile 64 x 64
    const int mbase = (wid >> 2) * 64;
    const int nbase = (wid & 3) * 64;

    uint32_t acc[4][8][2];        // f16x2 pairs; 64 regs
    #pragma unroll
    for (int mt = 0; mt < 4; mt++)
        #pragma unroll
        for (int ntl = 0; ntl < 8; ntl++) { acc[mt][ntl][0] = 0u; acc[mt][ntl][1] = 0u; }

    const int a_roff = ((lane >> 3) & 1) * 8 + (lane & 7);
    const int a_coff = (lane >> 4);
    const int b_roff = ((lane >> 4) & 1) * 8 + (lane & 7);
    const int b_coff = ((lane >> 3) & 1);

    asm volatile("cp.async.wait_group 1;" ::: "memory");   // stage 0 ready
    __syncthreads();

    #pragma unroll
    for (int kb = 0; kb < 4; kb++) {       // 4 stages of BK=64
        const uint32_t sA = smem_tiles + (kb & 1) * STAGE_BYTES;
        const uint32_t sB = sA + TILE_A_BYTES;

        #pragma unroll
        for (int ks = 0; ks < 4; ks++) {   // four k16 steps per stage
            uint32_t aF[4][4];
            #pragma unroll
            for (int mt = 0; mt < 4; mt++) {
                int r  = mbase + mt * 16 + a_roff;
                int ch = a_coff + 2 * ks;
                uint32_t addr = sA + r * 128 + (((ch ^ (r & 7)) & 7) << 4);
                asm volatile("ldmatrix.sync.aligned.m8n8.x4.shared.b16 {%0,%1,%2,%3}, [%4];"
                             : "=r"(aF[mt][0]), "=r"(aF[mt][1]),
                               "=r"(aF[mt][2]), "=r"(aF[mt][3])
                             : "r"(addr));
            }
            uint32_t bF[8][2];
            #pragma unroll
            for (int p = 0; p < 4; p++) {
                int r  = nbase + p * 16 + b_roff;
                int ch = b_coff + 2 * ks;
                uint32_t addr = sB + r * 128 + (((ch ^ (r & 7)) & 7) << 4);
                asm volatile("ldmatrix.sync.aligned.m8n8.x4.shared.b16 {%0,%1,%2,%3}, [%4];"
                             : "=r"(bF[2 * p][0]), "=r"(bF[2 * p][1]),
                               "=r"(bF[2 * p + 1][0]), "=r"(bF[2 * p + 1][1])
                             : "r"(addr));
            }
            #pragma unroll
            for (int mt = 0; mt < 4; mt++)
                #pragma unroll
                for (int ntl = 0; ntl < 8; ntl++)
                    asm volatile(
                        "mma.sync.aligned.m16n8k16.row.col.f16.f16.f16.f16 "
                        "{%0,%1}, {%2,%3,%4,%5}, {%6,%7}, {%0,%1};"
                        : "+r"(acc[mt][ntl][0]), "+r"(acc[mt][ntl][1])
                        : "r"(aF[mt][0]), "r"(aF[mt][1]),
                          "r"(aF[mt][2]), "r"(aF[mt][3]),
                          "r"(bF[ntl][0]), "r"(bF[ntl][1]));
        }

        if (kb < 3) {
            // next stage (kb+1) must be resident; then refill buffer kb&1
            asm volatile("cp.async.wait_group 0;" ::: "memory");
            __syncthreads();
            if (kb < 2) load_stage(kb + 2, kb & 1);
        }
    }

    // epilogue: unpack f16 acc -> dist -> hinge/mask -> sum over gi < gj
    const int gid = lane >> 2;
    const int tig = lane & 3;
    const bool need_mask = (bi >= 2 * bj);   // straddles the global diagonal
    float lsum = 0.0f;
    #pragma unroll
    for (int mt = 0; mt < 4; mt++) {
        #pragma unroll
        for (int ntl = 0; ntl < 8; ntl++) {
            #pragma unroll
            for (int h = 0; h < 2; h++) {
                float2 gp = __half22float2(*(const __half2*)&acc[mt][ntl][h]);
                int m = mbase + mt * 16 + gid + h * 8;
                float sqm = s_sqi[m];
                int   tm  = s_ti[m];
                #pragma unroll
                for (int q = 0; q < 2; q++) {
                    int nn = nbase + ntl * 8 + 2 * tig + q;
                    float g    = q ? gp.y : gp.x;
                    float dist = fmaf(-2.0f, g, sqm + s_sqj[nn]);
                    float val  = (tm == s_tj[nn]) ? dist : fmaxf(MARGIN - dist, 0.0f);
                    if (!need_mask || (iBase + m < jBase + nn)) lsum += val;
                }
            }
        }
    }

    s_red[tid] = lsum;
    __syncthreads();
    #pragma unroll
    for (int s = NTHREADS / 2; s > 32; s >>= 1) {
        if (tid < s) s_red[tid] += s_red[tid + s];
        __syncthreads();
    }
    if (tid < 32) {
        float v = s_red[tid] + s_red[tid + 32];
        #pragma unroll
        for (int o = 16; o > 0; o >>= 1) v += __shfl_xor_sync(0xffffffffu, v, o);
        if (tid == 0) atomicAdd(out, v * scale);
    }
}

extern "C" void kernel_launch(void* const* d_in, const int* in_sizes, int n_in,
                              void* d_out, int out_size) {
    const float* x   = (const float*)d_in[0];
    const void*  tgt = d_in[1];
    float*       out = (float*)d_out;

    int n = in_sizes[1];            // 8192
    int ntN = n / BN;               // 32 col-blocks
    int ngrid = ntN * (ntN + 1);    // sum(2bj+2) = 32*33 = 1056

    static int smem_set = 0;
    if (!smem_set) {
        cudaFuncSetAttribute(loss_kernel, cudaFuncAttributeMaxDynamicSharedMemorySize, SM_TOTAL);
        smem_set = 1;
    }

    cvtsq_kernel<<<(n + 7) / 8, 256>>>(x, (const unsigned int*)tgt, n, out);

    float scale = (float)(1.0 / ((double)n * ((double)n - 1.0)));
    loss_kernel<<<ngrid, NTHREADS, SM_TOTAL>>>(tgt, out, scale);
}

// round 13
// speedup vs baseline: 1.1101x; 1.1101x over previous
#include <cuda_runtime.h>
#include <cuda_fp16.h>
#include <cstdint>

#define N_MAX 8192
#define D_MAX 256
#define BM 128                    // CTA rows (i), A-resident
#define BN 128                    // tile cols (j)
#define BK 64                     // f16 K per B stage
#define TJ 4                      // j-tiles per CTA group
#define NTHREADS 256
#define MARGIN 0.5f

__device__ __half g_xh[N_MAX * D_MAX];
__device__ float g_sq[N_MAX];
__device__ int   g_is64;

// dynamic smem layout (bytes)
#define SM_A     0                                  // 4 sub-tiles x 16KB = 65536
#define SM_B     65536                              // 2 stage bufs x 16KB = 32768
#define SM_SQI   98304                              // 128*4
#define SM_TI    98816                               // 128*4
#define SM_SQJ   99328                              // TJ*128*4 = 2048
#define SM_TJ    101376                             // 2048
#define SM_RED   103424                             // 1024
#define SM_TOTAL 104448                             // 102 KB -> 2 CTAs/SM

__device__ __forceinline__ uint32_t smem_u32(const void* p) {
    uint32_t a;
    asm("{ .reg .u64 t; cvta.to.shared.u64 t, %1; cvt.u32.u64 %0, t; }" : "=r"(a) : "l"(p));
    return a;
}

// ---------------------------------------------------------------------------
// fused prelim: zero out + int64 detect + exact fp32 norms + f16 copy
// ---------------------------------------------------------------------------
__global__ void cvtsq_kernel(const float* __restrict__ x,
                             const unsigned int* __restrict__ t, int n,
                             float* __restrict__ out) {
    if (blockIdx.x == 0 && threadIdx.x < 32) {
        int lane = threadIdx.x;
        unsigned bad = t[2 * lane + 1] | t[2 * (lane + 32) + 1];
        unsigned ball = __ballot_sync(0xffffffffu, bad != 0u);
        if (lane == 0) { g_is64 = (ball == 0u); out[0] = 0.0f; }
    }

    int row  = blockIdx.x * (blockDim.x >> 5) + (threadIdx.x >> 5);
    int lane = threadIdx.x & 31;
    if (row >= n) return;
    const float* p = x + (size_t)row * D_MAX;

    float4 v0 = *(const float4*)(p + lane * 4);
    float4 v1 = *(const float4*)(p + 128 + lane * 4);

    float s = v0.x * v0.x + v0.y * v0.y + v0.z * v0.z + v0.w * v0.w
            + v1.x * v1.x + v1.y * v1.y + v1.z * v1.z + v1.w * v1.w;
    #pragma unroll
    for (int o = 16; o > 0; o >>= 1) s += __shfl_xor_sync(0xffffffffu, s, o);
    if (lane == 0) g_sq[row] = s;

    __half* dst = g_xh + (size_t)row * D_MAX;
    *(__half2*)(dst + lane * 4)           = __floats2half2_rn(v0.x, v0.y);
    *(__half2*)(dst + lane * 4 + 2)       = __floats2half2_rn(v0.z, v0.w);
    *(__half2*)(dst + 128 + lane * 4)     = __floats2half2_rn(v1.x, v1.y);
    *(__half2*)(dst + 128 + lane * 4 + 2) = __floats2half2_rn(v1.z, v1.w);
}

// ---------------------------------------------------------------------------
// f16 mma.sync fused gram + loss, A-resident multi-tile CTA.
// CTA: rows [128bi,128bi+128) vs up to TJ=4 j-tiles starting at bj0=bi+4g.
// A (128 x 256) resident as 4 swizzled 16KB sub-tiles; B streamed (16KB
// stages, 2 buffers, continuous across tiles). 8 warps (2m x 4n), warp 64x32,
// frag double-buffer inside stages. 2 CTAs/SM.
// smem sub-tile rows: 128B stride; chunk c of row r at r*128 + ((c^(r&7))<<4).
// ---------------------------------------------------------------------------
__global__ __launch_bounds__(NTHREADS, 2)
void loss_kernel(const void* __restrict__ tgt_raw, float* __restrict__ out,
                 int nt, float scale) {
    // decode blockIdx -> (bi, group): c(bi) = ceil((nt-bi)/TJ)
    int rem = blockIdx.x, bi = 0;
    for (;;) { int c = (nt - bi + TJ - 1) >> 2; if (rem < c) break; rem -= c; ++bi; }
    const int bj0   = bi + TJ * rem;
    const int ntile = min(TJ, nt - bj0);

    extern __shared__ char smem[];
    float* s_sqi = (float*)(smem + SM_SQI);
    int*   s_ti  = (int*)(smem + SM_TI);
    float* s_sqj = (float*)(smem + SM_SQJ);
    int*   s_tj  = (int*)(smem + SM_TJ);
    float* s_red = (float*)(smem + SM_RED);

    const int tid  = threadIdx.x;
    const int wid  = tid >> 5;
    const int lane = tid & 31;
    const int iBase = bi * BM;

    const uint32_t smem_base = smem_u32(smem);
    const __half* xa = g_xh + (size_t)iBase * D_MAX;

    // ---- prologue: A (all 4 sub-tiles, one group) + B stage 0 ----
    #pragma unroll
    for (int kb = 0; kb < 4; kb++) {
        #pragma unroll
        for (int u = 0; u < 4; u++) {
            int idx = tid * 4 + u;
            int row = idx >> 3;
            int c   = idx & 7;
            uint32_t sw = row * 128 + (((c ^ (row & 7)) & 7) << 4);
            asm volatile("cp.async.cg.shared.global [%0], [%1], 16;"
                         :: "r"(smem_base + SM_A + kb * 16384 + sw),
                            "l"((const void*)(xa + row * D_MAX + kb * BK + c * 8)) : "memory");
        }
    }
    asm volatile("cp.async.commit_group;" ::: "memory");

    auto load_B = [&](int S) {   // stage S: tile S>>2, k-chunk S&3, buffer S&1
        const __half* xb = g_xh + (size_t)(bj0 + (S >> 2)) * BN * D_MAX;
        const int k0 = (S & 3) * BK;
        const uint32_t sB = smem_base + SM_B + (S & 1) * 16384;
        #pragma unroll
        for (int u = 0; u < 4; u++) {
            int idx = tid * 4 + u;
            int row = idx >> 3;
            int c   = idx & 7;
            uint32_t sw = row * 128 + (((c ^ (row & 7)) & 7) << 4);
            asm volatile("cp.async.cg.shared.global [%0], [%1], 16;"
                         :: "r"(sB + sw), "l"((const void*)(xb + row * D_MAX + k0 + c * 8)) : "memory");
        }
        asm volatile("cp.async.commit_group;" ::: "memory");
    };
    load_B(0);

    // metadata (overlaps cp.async)
    {
        const long long* t64p = (const long long*)tgt_raw;
        const int*       t32p = (const int*)tgt_raw;
        const bool is64 = (g_is64 != 0);
        if (tid < BM) {
            s_sqi[tid] = g_sq[iBase + tid];
            s_ti[tid]  = is64 ? (int)t64p[iBase + tid] : t32p[iBase + tid];
        } else {
            int tt = tid - BM;   // 0..127
            #pragma unroll
            for (int jt = 0; jt < TJ; jt++) {
                if (jt < ntile) {
                    int gj = (bj0 + jt) * BN + tt;
                    s_sqj[jt * BN + tt] = g_sq[gj];
                    s_tj[jt * BN + tt]  = is64 ? (int)t64p[gj] : t32p[gj];
                }
            }
        }
    }

    // warp grid 2m x 4n; warp tile 64 x 32
    const int mbase = (wid >> 2) * 64;
    const int nbase = (wid & 3) * 32;

    const int a_roff = ((lane >> 3) & 1) * 8 + (lane & 7);
    const int a_coff = (lane >> 4);
    const int b_roff = ((lane >> 4) & 1) * 8 + (lane & 7);
    const int b_coff = ((lane >> 3) & 1);

    uint32_t aF[2][4][4];
    uint32_t bF[2][2][2];

    auto ldm_a = [&](int d, int kb, int ks) {
        const uint32_t sA = smem_base + SM_A + kb * 16384;
        #pragma unroll
        for (int mt = 0; mt < 4; mt++) {
            int r  = mbase + mt * 16 + a_roff;
            int ch = a_coff + 2 * ks;
            uint32_t addr = sA + r * 128 + (((ch ^ (r & 7)) & 7) << 4);
            asm volatile("ldmatrix.sync.aligned.m8n8.x4.shared.b16 {%0,%1,%2,%3}, [%4];"
                         : "=r"(aF[d][mt][0]), "=r"(aF[d][mt][1]),
                           "=r"(aF[d][mt][2]), "=r"(aF[d][mt][3])
                         : "r"(addr));
        }
    };
    auto ldm_b = [&](int d, int buf, int ks) {
        const uint32_t sB = smem_base + SM_B + buf * 16384;
        #pragma unroll
        for (int p = 0; p < 1; p++) {}   // (kept trivial; B needs 1 x4-load)
        {
            int r  = nbase + b_roff;      // pair p=0 covers rows nbase..nbase+15
            int ch = b_coff + 2 * ks;
            uint32_t addr = sB + r * 128 + (((ch ^ (r & 7)) & 7) << 4);
            asm volatile("ldmatrix.sync.aligned.m8n8.x4.shared.b16 {%0,%1,%2,%3}, [%4];"
                         : "=r"(bF[d][0][0]), "=r"(bF[d][0][1]),
                           "=r"(bF[d][1][0]), "=r"(bF[d][1][1])
                         : "r"(addr));
        }
        {
            int r  = nbase + 16 + b_roff; // second 16-col pair of the 32-wide tile
            int ch = b_coff + 2 * ks;
            uint32_t addr = sB + r * 128 + (((ch ^ (r & 7)) & 7) << 4);
            asm volatile("ldmatrix.sync.aligned.m8n8.x4.shared.b16 {%0,%1,%2,%3}, [%4];"
                         : "=r"(bF[d][0][0]), "=r"(bF[d][0][1]),
                           "=r"(bF[d][1][0]), "=r"(bF[d][1][1])
                         : "r"(addr));
        }
    };
    // NOTE: warp tile is 64x32 -> B covers rows nbase..nbase+31 = two x4 loads
    // into 4 fragment pairs. Rewritten properly below (bFv).
    (void)ldm_b;

    uint32_t bFv[2][4][2];
    auto ldm_bv = [&](int d, int buf, int ks) {
        const uint32_t sB = smem_base + SM_B + buf * 16384;
        #pragma unroll
        for (int p = 0; p < 2; p++) {
            int r  = nbase + p * 16 + b_roff;
            int ch = b_coff + 2 * ks;
            uint32_t addr = sB + r * 128 + (((ch ^ (r & 7)) & 7) << 4);
            asm volatile("ldmatrix.sync.aligned.m8n8.x4.shared.b16 {%0,%1,%2,%3}, [%4];"
                         : "=r"(bFv[d][2 * p][0]), "=r"(bFv[d][2 * p][1]),
                           "=r"(bFv[d][2 * p + 1][0]), "=r"(bFv[d][2 * p + 1][1])
                         : "r"(addr));
        }
    };

    uint32_t acc[4][4][2];
    auto mma_all = [&](int d) {
        #pragma unroll
        for (int mt = 0; mt < 4; mt++)
            #pragma unroll
            for (int ntl = 0; ntl < 4; ntl++)
                asm volatile(
                    "mma.sync.aligned.m16n8k16.row.col.f16.f16.f16.f16 "
                    "{%0,%1}, {%2,%3,%4,%5}, {%6,%7}, {%0,%1};"
                    : "+r"(acc[mt][ntl][0]), "+r"(acc[mt][ntl][1])
                    : "r"(aF[d][mt][0]), "r"(aF[d][mt][1]),
                      "r"(aF[d][mt][2]), "r"(aF[d][mt][3]),
                      "r"(bFv[d][ntl][0]), "r"(bFv[d][ntl][1]));
    };

    const int gid = lane >> 2;
    const int tig = lane & 3;
    float lsum = 0.0f;

    // ---- tile loop: continuous B stream ----
    for (int jt = 0; jt < ntile; jt++) {
        #pragma unroll
        for (int mt = 0; mt < 4; mt++)
            #pragma unroll
            for (int ntl = 0; ntl < 4; ntl++) { acc[mt][ntl][0] = 0u; acc[mt][ntl][1] = 0u; }

        #pragma unroll
        for (int kb = 0; kb < 4; kb++) {
            const int S = jt * 4 + kb;
            asm volatile("cp.async.wait_group 0;" ::: "memory");
            __syncthreads();
            if (S + 1 < ntile * 4) load_B(S + 1);

            const int buf = S & 1;
            ldm_a(0, kb, 0);
            ldm_bv(0, buf, 0);
            #pragma unroll
            for (int ks = 0; ks < 4; ks++) {
                const int cur = ks & 1, nxt = cur ^ 1;
                if (ks < 3) { ldm_a(nxt, kb, ks + 1); ldm_bv(nxt, buf, ks + 1); }
                mma_all(cur);
            }
            __syncthreads();   // all warps done with buf before it's refilled
        }

        // per-tile epilogue: accumulate into lsum
        const bool diag = (bj0 + jt == bi);
        #pragma unroll
        for (int mt = 0; mt < 4; mt++) {
            #pragma unroll
            for (int ntl = 0; ntl < 4; ntl++) {
                #pragma unroll
                for (int h = 0; h < 2; h++) {
                    float2 gp = __half22float2(*(const __half2*)&acc[mt][ntl][h]);
                    int m = mbase + mt * 16 + gid + h * 8;
                    float sqm = s_sqi[m];
                    int   tm  = s_ti[m];
                    #pragma unroll
                    for (int q = 0; q < 2; q++) {
                        int nn = nbase + ntl * 8 + 2 * tig + q;
                        float g    = q ? gp.y : gp.x;
                        float dist = fmaf(-2.0f, g, sqm + s_sqj[jt * BN + nn]);
                        float val  = (tm == s_tj[jt * BN + nn]) ? dist
                                                                : fmaxf(MARGIN - dist, 0.0f);
                        if (!diag || (m < nn)) lsum += val;
                    }
                }
            }
        }
    }

    // final block reduce + one atomic per CTA
    s_red[tid] = lsum;
    __syncthreads();
    #pragma unroll
    for (int s = NTHREADS / 2; s > 32; s >>= 1) {
        if (tid < s) s_red[tid] += s_red[tid + s];
        __syncthreads();
    }
    if (tid < 32) {
        float v = s_red[tid] + s_red[tid + 32];
        #pragma unroll
        for (int o = 16; o > 0; o >>= 1) v += __shfl_xor_sync(0xffffffffu, v, o);
        if (tid == 0) atomicAdd(out, v * scale);
    }
}

extern "C" void kernel_launch(void* const* d_in, const int* in_sizes, int n_in,
                              void* d_out, int out_size) {
    const float* x   = (const float*)d_in[0];
    const void*  tgt = d_in[1];
    float*       out = (float*)d_out;

    int n = in_sizes[1];            // 8192
    int nt = n / BM;                // 64
    int ngrid = 0;
    for (int b = 0; b < nt; b++) ngrid += (nt - b + TJ - 1) / TJ;   // 544

    static int smem_set = 0;
    if (!smem_set) {
        cudaFuncSetAttribute(loss_kernel, cudaFuncAttributeMaxDynamicSharedMemorySize, SM_TOTAL);
        smem_set = 1;
    }

    cvtsq_kernel<<<(n + 7) / 8, 256>>>(x, (const unsigned int*)tgt, n, out);

    float scale = (float)(1.0 / ((double)n * ((double)n - 1.0)));
    loss_kernel<<<ngrid, NTHREADS, SM_TOTAL>>>(tgt, out, nt, scale);
}

// round 14
// speedup vs baseline: 1.1444x; 1.0309x over previous
#include <cuda_runtime.h>
#include <cuda_fp16.h>
#include <cstdint>

#define N_MAX 8192
#define D_MAX 256
#define BM 128                    // CTA rows (i), A-resident
#define BN 128                    // tile cols (j)
#define BK 64                     // f16 K per B stage
#define TJ 2                      // j-tiles per CTA group
#define NTHREADS 256
#define MARGIN 0.5f

__device__ __half g_xh[N_MAX * D_MAX];
__device__ float g_sq[N_MAX];
__device__ int   g_is64;

// dynamic smem layout (bytes)
#define SM_A     0                                  // 4 sub-tiles x 16KB
#define SM_B     65536                              // 2 bufs x 16KB
#define SM_SQI   98304
#define SM_TI    98816
#define SM_SQJ   99328                              // TJ*128*4
#define SM_TJ    100352
#define SM_RED   101376
#define SM_TOTAL 102400                             // 100 KB -> 2 CTAs/SM

__device__ __forceinline__ uint32_t smem_u32(const void* p) {
    uint32_t a;
    asm("{ .reg .u64 t; cvta.to.shared.u64 t, %1; cvt.u32.u64 %0, t; }" : "=r"(a) : "l"(p));
    return a;
}

// ---------------------------------------------------------------------------
// fused prelim: zero out + int64 detect + exact fp32 norms + f16 copy
// ---------------------------------------------------------------------------
__global__ void cvtsq_kernel(const float* __restrict__ x,
                             const unsigned int* __restrict__ t, int n,
                             float* __restrict__ out) {
    if (blockIdx.x == 0 && threadIdx.x < 32) {
        int lane = threadIdx.x;
        unsigned bad = t[2 * lane + 1] | t[2 * (lane + 32) + 1];
        unsigned ball = __ballot_sync(0xffffffffu, bad != 0u);
        if (lane == 0) { g_is64 = (ball == 0u); out[0] = 0.0f; }
    }

    int row  = blockIdx.x * (blockDim.x >> 5) + (threadIdx.x >> 5);
    int lane = threadIdx.x & 31;
    if (row >= n) return;
    const float* p = x + (size_t)row * D_MAX;

    float4 v0 = *(const float4*)(p + lane * 4);
    float4 v1 = *(const float4*)(p + 128 + lane * 4);

    float s = v0.x * v0.x + v0.y * v0.y + v0.z * v0.z + v0.w * v0.w
            + v1.x * v1.x + v1.y * v1.y + v1.z * v1.z + v1.w * v1.w;
    #pragma unroll
    for (int o = 16; o > 0; o >>= 1) s += __shfl_xor_sync(0xffffffffu, s, o);
    if (lane == 0) g_sq[row] = s;

    __half* dst = g_xh + (size_t)row * D_MAX;
    *(__half2*)(dst + lane * 4)           = __floats2half2_rn(v0.x, v0.y);
    *(__half2*)(dst + lane * 4 + 2)       = __floats2half2_rn(v0.z, v0.w);
    *(__half2*)(dst + 128 + lane * 4)     = __floats2half2_rn(v1.x, v1.y);
    *(__half2*)(dst + 128 + lane * 4 + 2) = __floats2half2_rn(v1.z, v1.w);
}

// ---------------------------------------------------------------------------
// f16 mma.sync fused gram + loss, A-resident TJ=2 multi-tile CTA.
// CTA: rows [128bi,..+128) vs tiles bj0, bj0+1 (bj0 = bi + 2*rem).
// A resident (4 x 16KB sub-tiles); B streamed (16KB stages, 2 bufs, 1 sync
// per stage). 8 warps (2m x 4n), warp 64x32, frag double-buffer, XOR-addr.
// smem rows: 128B stride; chunk c of row r at r*128 + ((c^(r&7))<<4).
// addr(ks) = addr(0) ^ (ks<<5)  [ch = coff ^ 2ks, XOR distributes].
// ---------------------------------------------------------------------------
__global__ __launch_bounds__(NTHREADS, 2)
void loss_kernel(const void* __restrict__ tgt_raw, float* __restrict__ out,
                 int nt, float scale) {
    // decode blockIdx -> (bi, rem): count(bi) = ceil((nt-bi)/TJ)
    int rem = blockIdx.x, bi = 0;
    for (;;) { int c = (nt - bi + 1) >> 1; if (rem < c) break; rem -= c; ++bi; }
    const int bj0   = bi + TJ * rem;
    const int ntile = min(TJ, nt - bj0);

    extern __shared__ char smem[];
    float* s_sqi = (float*)(smem + SM_SQI);
    int*   s_ti  = (int*)(smem + SM_TI);
    float* s_sqj = (float*)(smem + SM_SQJ);
    int*   s_tj  = (int*)(smem + SM_TJ);
    float* s_red = (float*)(smem + SM_RED);

    const int tid  = threadIdx.x;
    const int wid  = tid >> 5;
    const int lane = tid & 31;
    const int iBase = bi * BM;

    const uint32_t smem_base = smem_u32(smem);
    const __half* xa = g_xh + (size_t)iBase * D_MAX;

    // ---- prologue: A (one group) + B stage 0 ----
    #pragma unroll
    for (int kb = 0; kb < 4; kb++) {
        #pragma unroll
        for (int u = 0; u < 4; u++) {
            int idx = tid * 4 + u;
            int row = idx >> 3;
            int c   = idx & 7;
            uint32_t sw = row * 128 + (((c ^ (row & 7)) & 7) << 4);
            asm volatile("cp.async.cg.shared.global [%0], [%1], 16;"
                         :: "r"(smem_base + SM_A + kb * 16384 + sw),
                            "l"((const void*)(xa + row * D_MAX + kb * BK + c * 8)) : "memory");
        }
    }
    asm volatile("cp.async.commit_group;" ::: "memory");

    auto load_B = [&](int S) {   // stage S: tile S>>2, k-chunk S&3, buffer S&1
        const __half* xb = g_xh + (size_t)(bj0 + (S >> 2)) * BN * D_MAX;
        const int k0 = (S & 3) * BK;
        const uint32_t sB = smem_base + SM_B + (S & 1) * 16384;
        #pragma unroll
        for (int u = 0; u < 4; u++) {
            int idx = tid * 4 + u;
            int row = idx >> 3;
            int c   = idx & 7;
            uint32_t sw = row * 128 + (((c ^ (row & 7)) & 7) << 4);
            asm volatile("cp.async.cg.shared.global [%0], [%1], 16;"
                         :: "r"(sB + sw), "l"((const void*)(xb + row * D_MAX + k0 + c * 8)) : "memory");
        }
        asm volatile("cp.async.commit_group;" ::: "memory");
    };
    load_B(0);

    // metadata (overlaps cp.async)
    {
        const long long* t64p = (const long long*)tgt_raw;
        const int*       t32p = (const int*)tgt_raw;
        const bool is64 = (g_is64 != 0);
        if (tid < BM) {
            s_sqi[tid] = g_sq[iBase + tid];
            s_ti[tid]  = is64 ? (int)t64p[iBase + tid] : t32p[iBase + tid];
        } else {
            int tt = tid - BM;   // 0..127
            #pragma unroll
            for (int jt = 0; jt < TJ; jt++) {
                if (jt < ntile) {
                    int gj = (bj0 + jt) * BN + tt;
                    s_sqj[jt * BN + tt] = g_sq[gj];
                    s_tj[jt * BN + tt]  = is64 ? (int)t64p[gj] : t32p[gj];
                }
            }
        }
    }

    // warp grid 2m x 4n; warp tile 64 x 32
    const int mbase = (wid >> 2) * 64;
    const int nbase = (wid & 3) * 32;

    const int a_roff = ((lane >> 3) & 1) * 8 + (lane & 7);
    const int a_coff = (lane >> 4);
    const int b_roff = ((lane >> 4) & 1) * 8 + (lane & 7);
    const int b_coff = ((lane >> 3) & 1);

    uint32_t aF[2][4][4];
    uint32_t bF[2][4][2];
    uint32_t acc[4][4][2];

    const int gid = lane >> 2;
    const int tig = lane & 3;
    float lsum = 0.0f;

    // ---- tile loop; B stream continuous, one sync per stage ----
    for (int jt = 0; jt < ntile; jt++) {
        #pragma unroll
        for (int mt = 0; mt < 4; mt++)
            #pragma unroll
            for (int ntl = 0; ntl < 4; ntl++) { acc[mt][ntl][0] = 0u; acc[mt][ntl][1] = 0u; }

        #pragma unroll
        for (int kb = 0; kb < 4; kb++) {
            const int S = jt * 4 + kb;
            // B(S) resident; also orders: all warps finished reading buf S&1
            // at stage S-2 (they passed stage S-1's sync), so refill is safe.
            asm volatile("cp.async.wait_group 0;" ::: "memory");
            __syncthreads();
            if (S + 1 < ntile * 4) load_B(S + 1);

            // per-stage base addresses (ks=0); addr(ks) = base ^ (ks<<5)
            const uint32_t sA = smem_base + SM_A + kb * 16384;
            const uint32_t sB = smem_base + SM_B + (S & 1) * 16384;
            uint32_t abase[4], bbase[2];
            #pragma unroll
            for (int mt = 0; mt < 4; mt++) {
                int r = mbase + mt * 16 + a_roff;
                abase[mt] = sA + r * 128 + (((a_coff ^ (r & 7)) & 7) << 4);
            }
            #pragma unroll
            for (int p = 0; p < 2; p++) {
                int r = nbase + p * 16 + b_roff;
                bbase[p] = sB + r * 128 + (((b_coff ^ (r & 7)) & 7) << 4);
            }

            auto ldm = [&](int d, int ks) {
                #pragma unroll
                for (int mt = 0; mt < 4; mt++)
                    asm volatile("ldmatrix.sync.aligned.m8n8.x4.shared.b16 {%0,%1,%2,%3}, [%4];"
                                 : "=r"(aF[d][mt][0]), "=r"(aF[d][mt][1]),
                                   "=r"(aF[d][mt][2]), "=r"(aF[d][mt][3])
                                 : "r"(abase[mt] ^ (unsigned)(ks << 5)));
                #pragma unroll
                for (int p = 0; p < 2; p++)
                    asm volatile("ldmatrix.sync.aligned.m8n8.x4.shared.b16 {%0,%1,%2,%3}, [%4];"
                                 : "=r"(bF[d][2 * p][0]), "=r"(bF[d][2 * p][1]),
                                   "=r"(bF[d][2 * p + 1][0]), "=r"(bF[d][2 * p + 1][1])
                                 : "r"(bbase[p] ^ (unsigned)(ks << 5)));
            };
            auto mma_all = [&](int d) {
                #pragma unroll
                for (int mt = 0; mt < 4; mt++)
                    #pragma unroll
                    for (int ntl = 0; ntl < 4; ntl++)
                        asm volatile(
                            "mma.sync.aligned.m16n8k16.row.col.f16.f16.f16.f16 "
                            "{%0,%1}, {%2,%3,%4,%5}, {%6,%7}, {%0,%1};"
                            : "+r"(acc[mt][ntl][0]), "+r"(acc[mt][ntl][1])
                            : "r"(aF[d][mt][0]), "r"(aF[d][mt][1]),
                              "r"(aF[d][mt][2]), "r"(aF[d][mt][3]),
                              "r"(bF[d][ntl][0]), "r"(bF[d][ntl][1]));
            };

            ldm(0, 0);
            #pragma unroll
            for (int ks = 0; ks < 4; ks++) {
                const int cur = ks & 1;
                if (ks < 3) ldm(cur ^ 1, ks + 1);
                mma_all(cur);
            }
            // no trailing sync: next stage's post-wait sync provides ordering
        }

        // per-tile epilogue: accumulate into lsum (registers only)
        const bool diag = (bj0 + jt == bi);
        #pragma unroll
        for (int mt = 0; mt < 4; mt++) {
            #pragma unroll
            for (int ntl = 0; ntl < 4; ntl++) {
                #pragma unroll
                for (int h = 0; h < 2; h++) {
                    float2 gp = __half22float2(*(const __half2*)&acc[mt][ntl][h]);
                    int m = mbase + mt * 16 + gid + h * 8;
                    float sqm = s_sqi[m];
                    int   tm  = s_ti[m];
                    #pragma unroll
                    for (int q = 0; q < 2; q++) {
                        int nn = nbase + ntl * 8 + 2 * tig + q;
                        float g    = q ? gp.y : gp.x;
                        float dist = fmaf(-2.0f, g, sqm + s_sqj[jt * BN + nn]);
                        float val  = (tm == s_tj[jt * BN + nn]) ? dist
                                                                : fmaxf(MARGIN - dist, 0.0f);
                        if (!diag || (m < nn)) lsum += val;
                    }
                }
            }
        }
    }

    // final block reduce + one atomic per CTA
    s_red[tid] = lsum;
    __syncthreads();
    #pragma unroll
    for (int s = NTHREADS / 2; s > 32; s >>= 1) {
        if (tid < s) s_red[tid] += s_red[tid + s];
        __syncthreads();
    }
    if (tid < 32) {
        float v = s_red[tid] + s_red[tid + 32];
        #pragma unroll
        for (int o = 16; o > 0; o >>= 1) v += __shfl_xor_sync(0xffffffffu, v, o);
        if (tid == 0) atomicAdd(out, v * scale);
    }
}

extern "C" void kernel_launch(void* const* d_in, const int* in_sizes, int n_in,
                              void* d_out, int out_size) {
    const float* x   = (const float*)d_in[0];
    const void*  tgt = d_in[1];
    float*       out = (float*)d_out;

    int n = in_sizes[1];            // 8192
    int nt = n / BM;                // 64
    int ngrid = 0;
    for (int b = 0; b < nt; b++) ngrid += (nt - b + 1) / 2 + ((nt - b) & 1 ? 0 : 0);
    ngrid = 0;
    for (int b = 0; b < nt; b++) ngrid += (nt - b + TJ - 1) / TJ;   // 1056

    static int smem_set = 0;
    if (!smem_set) {
        cudaFuncSetAttribute(loss_kernel, cudaFuncAttributeMaxDynamicSharedMemorySize, SM_TOTAL);
        smem_set = 1;
    }

    cvtsq_kernel<<<(n + 7) / 8, 256>>>(x, (const unsigned int*)tgt, n, out);

    float scale = (float)(1.0 / ((double)n * ((double)n - 1.0)));
    loss_kernel<<<ngrid, NTHREADS, SM_TOTAL>>>(tgt, out, nt, scale);
}